// round 8
// baseline (speedup 1.0000x reference)
#include <cuda_runtime.h>
#include <math.h>
#include <stdint.h>

#define S_LEN 2048
#define HID   4096
#define NH    32
#define NKV   8
#define HD    128
#define TOPK  16

// ---------------- scratch (device globals: no allocations allowed) ----------
__device__ float g_Q[(size_t)S_LEN * HID];        // 32 MB
__device__ float g_K[(size_t)S_LEN * NKV * HD];   // 8 MB
__device__ float g_V[(size_t)S_LEN * NKV * HD];   // 8 MB
__device__ float g_attn[(size_t)S_LEN * HID];     // 32 MB
__device__ float g_cos[S_LEN * 64];
__device__ float g_sin[S_LEN * 64];

// ---------------- RoPE table (host/correctly-rounded math emulation) --------
// DO NOT TOUCH: this exact pipeline is what makes the kernel pass.
__global__ void rope_table_kernel() {
    int idx = blockIdx.x * blockDim.x + threadIdx.x;
    if (idx >= S_LEN * 64) return;
    int s = idx >> 6;
    int i = idx & 63;
    double expo = (double)(2 * i) / 128.0;            // exact
    float  p    = (float)pow(500000.0, expo);         // CR powf emulation
    float  inv  = __fdiv_rn(1.0f, p);
    float  ang  = __fmul_rn((float)s, inv);
    g_cos[idx] = (float)cos((double)ang);             // CR cosf emulation
    g_sin[idx] = (float)sin((double)ang);             // CR sinf emulation
}

// ---------------- RoPE apply (in place, explicit rn mul/add, no FMA) --------
__global__ void rope_apply_kernel(float* __restrict__ X, int nheads) {
    int idx = blockIdx.x * blockDim.x + threadIdx.x;
    int total = S_LEN * nheads * 64;
    if (idx >= total) return;
    int i = idx & 63;
    int h = (idx >> 6) % nheads;
    int s = idx / (nheads * 64);
    size_t base = ((size_t)s * nheads + h) * HD + i;
    float c  = g_cos[(s << 6) + i];
    float sn = g_sin[(s << 6) + i];
    float x1 = X[base];
    float x2 = X[base + 64];
    float t1 = __fmul_rn(x1, c);
    float t2 = __fmul_rn(x2, sn);
    float u1 = __fmul_rn(x2, c);
    float u2 = __fmul_rn(x1, sn);
    X[base]      = __fadd_rn(t1, -t2);
    X[base + 64] = __fadd_rn(u1, u2);
}

// ---------------- fp32 SGEMM (PROVEN top-k-safe; used for Wq, Wk) ----------
// BM=BN=128, BK=16, 256 threads, 8x8 per thread, register prefetch.
__device__ __forceinline__ void sgemm_body(
    const float* __restrict__ A, const float* __restrict__ B,
    float* __restrict__ C, int M, int N, int K, int bm, int bn)
{
    __shared__ float As[16 * 132];  // [k][m], padded
    __shared__ float Bs[16 * 132];  // [k][n], padded

    const int tid = threadIdx.x;
    const int lr = tid >> 2;            // 0..63
    const int lc = (tid & 3) << 2;      // 0,4,8,12
    const int ty = tid >> 4;            // 0..15
    const int tx = tid & 15;            // 0..15

    float acc[8][8];
#pragma unroll
    for (int i = 0; i < 8; i++)
#pragma unroll
        for (int j = 0; j < 8; j++) acc[i][j] = 0.0f;

    const float* Ap = A + (size_t)(bm + lr) * K + lc;
    const float* Bp = B + (size_t)(bn + lr) * K + lc;

    float4 a0 = *(const float4*)(Ap);
    float4 a1 = *(const float4*)(Ap + (size_t)64 * K);
    float4 b0 = *(const float4*)(Bp);
    float4 b1 = *(const float4*)(Bp + (size_t)64 * K);

    for (int k0 = 0; k0 < K; k0 += 16) {
        __syncthreads();
        As[(lc + 0) * 132 + lr] = a0.x;
        As[(lc + 1) * 132 + lr] = a0.y;
        As[(lc + 2) * 132 + lr] = a0.z;
        As[(lc + 3) * 132 + lr] = a0.w;
        As[(lc + 0) * 132 + lr + 64] = a1.x;
        As[(lc + 1) * 132 + lr + 64] = a1.y;
        As[(lc + 2) * 132 + lr + 64] = a1.z;
        As[(lc + 3) * 132 + lr + 64] = a1.w;
        Bs[(lc + 0) * 132 + lr] = b0.x;
        Bs[(lc + 1) * 132 + lr] = b0.y;
        Bs[(lc + 2) * 132 + lr] = b0.z;
        Bs[(lc + 3) * 132 + lr] = b0.w;
        Bs[(lc + 0) * 132 + lr + 64] = b1.x;
        Bs[(lc + 1) * 132 + lr + 64] = b1.y;
        Bs[(lc + 2) * 132 + lr + 64] = b1.z;
        Bs[(lc + 3) * 132 + lr + 64] = b1.w;
        __syncthreads();

        if (k0 + 16 < K) {
            a0 = *(const float4*)(Ap + k0 + 16);
            a1 = *(const float4*)(Ap + (size_t)64 * K + k0 + 16);
            b0 = *(const float4*)(Bp + k0 + 16);
            b1 = *(const float4*)(Bp + (size_t)64 * K + k0 + 16);
        }

#pragma unroll
        for (int kk = 0; kk < 16; kk++) {
            float ar[8], br[8];
            *(float4*)(ar)     = *(float4*)&As[kk * 132 + ty * 8];
            *(float4*)(ar + 4) = *(float4*)&As[kk * 132 + ty * 8 + 4];
            *(float4*)(br)     = *(float4*)&Bs[kk * 132 + tx * 8];
            *(float4*)(br + 4) = *(float4*)&Bs[kk * 132 + tx * 8 + 4];
#pragma unroll
            for (int i = 0; i < 8; i++)
#pragma unroll
                for (int j = 0; j < 8; j++)
                    acc[i][j] = fmaf(ar[i], br[j], acc[i][j]);
        }
    }

#pragma unroll
    for (int i = 0; i < 8; i++) {
        size_t row = (size_t)(bm + ty * 8 + i) * N + bn + tx * 8;
        float4 v0 = make_float4(acc[i][0], acc[i][1], acc[i][2], acc[i][3]);
        float4 v1 = make_float4(acc[i][4], acc[i][5], acc[i][6], acc[i][7]);
        *(float4*)&C[row]     = v0;
        *(float4*)&C[row + 4] = v1;
    }
}

__global__ __launch_bounds__(256) void sgemm_nt(
    const float* __restrict__ A, const float* __restrict__ B,
    float* __restrict__ C, int M, int N, int K)
{
    sgemm_body(A, B, C, M, N, K, blockIdx.y * 128, blockIdx.x * 128);
}

// ---------------- TF32 helpers ----------------------------------------------
__device__ __forceinline__ uint32_t f32_to_tf32(float x) {
    uint32_t r;
    asm("cvt.rna.tf32.f32 %0, %1;" : "=r"(r) : "f"(x));
    return r;
}

__device__ __forceinline__ void mma_tf32(
    float& c0, float& c1, float& c2, float& c3,
    uint32_t a0, uint32_t a1, uint32_t a2, uint32_t a3,
    uint32_t b0, uint32_t b1)
{
    asm("mma.sync.aligned.m16n8k8.row.col.f32.tf32.tf32.f32 "
        "{%0,%1,%2,%3}, {%4,%5,%6,%7}, {%8,%9}, {%0,%1,%2,%3};"
        : "+f"(c0), "+f"(c1), "+f"(c2), "+f"(c3)
        : "r"(a0), "r"(a1), "r"(a2), "r"(a3), "r"(b0), "r"(b1));
}

// ---------------- 3xTF32 GEMM (top-k-SAFE paths only: Wv, Wo) --------------
// Block 128x128, BK=16, 256 threads = 8 warps (4 M x 2 N), warp tile 32x64.
#define GPAD 20  // BK + 4, fragment LDS conflict-free

__device__ __forceinline__ void gemm3xtf32_body(
    const float* __restrict__ A, const float* __restrict__ B,
    float* __restrict__ C, int M, int N, int K, int bm, int bn)
{
    __shared__ uint32_t Ah[128 * GPAD];
    __shared__ uint32_t Al[128 * GPAD];
    __shared__ uint32_t Bh[128 * GPAD];
    __shared__ uint32_t Bl[128 * GPAD];

    const int tid  = threadIdx.x;
    const int warp = tid >> 5;
    const int lane = tid & 31;
    const int wm   = warp & 3;        // 0..3 -> 32-row band
    const int wn   = warp >> 2;       // 0..1 -> 64-col band
    const int grp  = lane >> 2;       // 0..7
    const int tig  = lane & 3;        // 0..3

    float c[2][8][4];
#pragma unroll
    for (int mt = 0; mt < 2; mt++)
#pragma unroll
        for (int nt = 0; nt < 8; nt++)
#pragma unroll
            for (int r = 0; r < 4; r++) c[mt][nt][r] = 0.0f;

    const int lr = tid >> 2;            // 0..63
    const int lc = (tid & 3) << 2;      // 0,4,8,12
    const float* Ap = A + (size_t)(bm + lr) * K + lc;
    const float* Bp = B + (size_t)(bn + lr) * K + lc;

    float4 a0 = *(const float4*)(Ap);
    float4 a1 = *(const float4*)(Ap + (size_t)64 * K);
    float4 b0 = *(const float4*)(Bp);
    float4 b1 = *(const float4*)(Bp + (size_t)64 * K);

    for (int k0 = 0; k0 < K; k0 += 16) {
        __syncthreads();
        {
            const float av[8] = {a0.x, a0.y, a0.z, a0.w, a1.x, a1.y, a1.z, a1.w};
            const float bv[8] = {b0.x, b0.y, b0.z, b0.w, b1.x, b1.y, b1.z, b1.w};
#pragma unroll
            for (int e = 0; e < 8; e++) {
                int row = lr + (e >> 2) * 64;
                int col = lc + (e & 3);
                uint32_t hi = f32_to_tf32(av[e]);
                uint32_t lo = f32_to_tf32(av[e] - __uint_as_float(hi));
                Ah[row * GPAD + col] = hi;
                Al[row * GPAD + col] = lo;
                hi = f32_to_tf32(bv[e]);
                lo = f32_to_tf32(bv[e] - __uint_as_float(hi));
                Bh[row * GPAD + col] = hi;
                Bl[row * GPAD + col] = lo;
            }
        }
        __syncthreads();

        if (k0 + 16 < K) {
            a0 = *(const float4*)(Ap + k0 + 16);
            a1 = *(const float4*)(Ap + (size_t)64 * K + k0 + 16);
            b0 = *(const float4*)(Bp + k0 + 16);
            b1 = *(const float4*)(Bp + (size_t)64 * K + k0 + 16);
        }

#pragma unroll
        for (int kb = 0; kb < 16; kb += 8) {
            uint32_t ah[2][4], al[2][4];
#pragma unroll
            for (int mt = 0; mt < 2; mt++) {
                int row = wm * 32 + mt * 16 + grp;
                ah[mt][0] = Ah[row * GPAD + kb + tig];
                ah[mt][1] = Ah[(row + 8) * GPAD + kb + tig];
                ah[mt][2] = Ah[row * GPAD + kb + tig + 4];
                ah[mt][3] = Ah[(row + 8) * GPAD + kb + tig + 4];
                al[mt][0] = Al[row * GPAD + kb + tig];
                al[mt][1] = Al[(row + 8) * GPAD + kb + tig];
                al[mt][2] = Al[row * GPAD + kb + tig + 4];
                al[mt][3] = Al[(row + 8) * GPAD + kb + tig + 4];
            }
#pragma unroll
            for (int nt = 0; nt < 8; nt++) {
                int col = wn * 64 + nt * 8 + grp;
                uint32_t bh0 = Bh[col * GPAD + kb + tig];
                uint32_t bh1 = Bh[col * GPAD + kb + tig + 4];
                uint32_t bl0 = Bl[col * GPAD + kb + tig];
                uint32_t bl1 = Bl[col * GPAD + kb + tig + 4];
#pragma unroll
                for (int mt = 0; mt < 2; mt++) {
                    float* cc = c[mt][nt];
                    mma_tf32(cc[0], cc[1], cc[2], cc[3],
                             al[mt][0], al[mt][1], al[mt][2], al[mt][3], bh0, bh1);
                    mma_tf32(cc[0], cc[1], cc[2], cc[3],
                             ah[mt][0], ah[mt][1], ah[mt][2], ah[mt][3], bl0, bl1);
                    mma_tf32(cc[0], cc[1], cc[2], cc[3],
                             ah[mt][0], ah[mt][1], ah[mt][2], ah[mt][3], bh0, bh1);
                }
            }
        }
    }

#pragma unroll
    for (int mt = 0; mt < 2; mt++) {
#pragma unroll
        for (int nt = 0; nt < 8; nt++) {
            int row = bm + wm * 32 + mt * 16 + grp;
            int col = bn + wn * 64 + nt * 8 + 2 * tig;
            float2 v0 = make_float2(c[mt][nt][0], c[mt][nt][1]);
            float2 v1 = make_float2(c[mt][nt][2], c[mt][nt][3]);
            *(float2*)&C[(size_t)row * N + col]       = v0;
            *(float2*)&C[(size_t)(row + 8) * N + col] = v1;
        }
    }
}

__global__ __launch_bounds__(256) void gemm3xtf32(
    const float* __restrict__ A, const float* __restrict__ B,
    float* __restrict__ C, int M, int N, int K)
{
    gemm3xtf32_body(A, B, C, M, N, K, blockIdx.y * 128, blockIdx.x * 128);
}

// ---------------- fused top-k attention (PROVEN; unchanged) ----------------
__global__ __launch_bounds__(256) void attn_kernel(
    const float* __restrict__ Q, const float* __restrict__ Kd,
    const float* __restrict__ V, float* __restrict__ O)
{
    extern __shared__ float sm[];
    float* Qs = sm;                      // [64][132]
    float* Ks = Qs + 64 * 132;           // [64][132]
    float* Ss = Ks + 64 * 132;           // [64][64]
    float* Tv = Ss + 64 * 64;            // [64][16] values -> weights
    int*   Ti = (int*)(Tv + 64 * TOPK);  // [64][16]

    const int tid = threadIdx.x;
    const int h   = blockIdx.y;
    const int kvh = h >> 2;
    const int q0  = blockIdx.x * 64;
    const float sqrtd = 11.313708498984761f;  // f32(sqrt(128))

#pragma unroll
    for (int it = 0; it < 8; it++) {
        int idx = tid + it * 256;
        int r = idx >> 5;
        int d4 = (idx & 31) << 2;
        float4 v = *(const float4*)&Q[((size_t)(q0 + r) * NH + h) * HD + d4];
        *(float4*)&Qs[r * 132 + d4] = v;
    }
    if (tid < 64) {
#pragma unroll
        for (int j = 0; j < TOPK; j++) Tv[tid * TOPK + j] = -INFINITY;
    }
    float vmin = -INFINITY;
    int minpos = 0;

    const int ty = tid >> 4, tx = tid & 15;
    const int r0 = ty << 2, c0 = tx << 2;

    for (int kt = 0; kt < S_LEN / 64; kt++) {
        __syncthreads();
#pragma unroll
        for (int it = 0; it < 8; it++) {
            int idx = tid + it * 256;
            int r = idx >> 5;
            int d4 = (idx & 31) << 2;
            float4 v = *(const float4*)&Kd[((size_t)(kt * 64 + r) * NKV + kvh) * HD + d4];
            *(float4*)&Ks[r * 132 + d4] = v;
        }
        __syncthreads();

        float acc[4][4];
#pragma unroll
        for (int i = 0; i < 4; i++)
#pragma unroll
            for (int j = 0; j < 4; j++) acc[i][j] = 0.0f;

        const float* qp = Qs + r0 * 132;
        const float* kp = Ks + c0 * 132;
#pragma unroll
        for (int d = 0; d < 128; d += 4) {
            float4 A0 = *(const float4*)(qp + d);
            float4 A1 = *(const float4*)(qp + 132 + d);
            float4 A2 = *(const float4*)(qp + 264 + d);
            float4 A3 = *(const float4*)(qp + 396 + d);
            float4 B0 = *(const float4*)(kp + d);
            float4 B1 = *(const float4*)(kp + 132 + d);
            float4 B2 = *(const float4*)(kp + 264 + d);
            float4 B3 = *(const float4*)(kp + 396 + d);
            const float4 Ax[4] = {A0, A1, A2, A3};
            const float4 Bx[4] = {B0, B1, B2, B3};
#pragma unroll
            for (int i = 0; i < 4; i++)
#pragma unroll
                for (int j = 0; j < 4; j++) {
                    float t = acc[i][j];
                    t = fmaf(Ax[i].x, Bx[j].x, t);
                    t = fmaf(Ax[i].y, Bx[j].y, t);
                    t = fmaf(Ax[i].z, Bx[j].z, t);
                    t = fmaf(Ax[i].w, Bx[j].w, t);
                    acc[i][j] = t;
                }
        }
#pragma unroll
        for (int i = 0; i < 4; i++)
#pragma unroll
            for (int j = 0; j < 4; j++)
                Ss[(r0 + i) * 64 + c0 + j] = __fdiv_rn(acc[i][j], sqrtd);
        __syncthreads();

        if (tid < 64) {
            int base = kt * 64;
            float* tvp = Tv + tid * TOPK;
            int*   tip = Ti + tid * TOPK;
            const float* srow = Ss + tid * 64;
            for (int c = 0; c < 64; c++) {
                float s = srow[c];
                if (s > vmin) {
                    tvp[minpos] = s;
                    tip[minpos] = base + c;
                    vmin = tvp[0]; minpos = 0;
#pragma unroll
                    for (int j = 1; j < TOPK; j++) {
                        float t = tvp[j];
                        if (t < vmin) { vmin = t; minpos = j; }
                    }
                }
            }
        }
    }
    __syncthreads();

    if (tid < 64) {
        float* tvp = Tv + tid * TOPK;
        float m = -INFINITY;
#pragma unroll
        for (int j = 0; j < TOPK; j++) m = fmaxf(m, tvp[j]);
        float ssum = 0.0f;
#pragma unroll
        for (int j = 0; j < TOPK; j++) {
            float e = expf(tvp[j] - m);
            tvp[j] = e;
            ssum += e;
        }
        float inv = __fdiv_rn(1.0f, ssum);
#pragma unroll
        for (int j = 0; j < TOPK; j++) tvp[j] = __fmul_rn(tvp[j], inv);
    }
    __syncthreads();

#pragma unroll
    for (int it = 0; it < 32; it++) {
        int idx = tid + it * 256;
        int r = idx >> 7;
        int d = idx & 127;
        const float* tvp = Tv + r * TOPK;
        const int*   tip = Ti + r * TOPK;
        float acc = 0.0f;
#pragma unroll
        for (int j = 0; j < TOPK; j++) {
            float w = tvp[j];
            int ki = tip[j];
            acc = fmaf(w, V[((size_t)ki * NKV + kvh) * HD + d], acc);
        }
        O[((size_t)(q0 + r) * NH + h) * HD + d] = acc;
    }
}

// ---------------- launch ----------------------------------------------------
extern "C" void kernel_launch(void* const* d_in, const int* in_sizes, int n_in,
                              void* d_out, int out_size)
{
    const float* hidden = (const float*)d_in[0];
    const float* Wq = (const float*)d_in[1];
    const float* Wk = (const float*)d_in[2];
    const float* Wv = (const float*)d_in[3];
    const float* Wo = (const float*)d_in[4];
    float* out = (float*)d_out;

    float *q, *k, *v, *at;
    cudaGetSymbolAddress((void**)&q,  g_Q);
    cudaGetSymbolAddress((void**)&k,  g_K);
    cudaGetSymbolAddress((void**)&v,  g_V);
    cudaGetSymbolAddress((void**)&at, g_attn);

    rope_table_kernel<<<(S_LEN * 64 + 255) / 256, 256>>>();

    dim3 gq(HID / 128, S_LEN / 128);        // (32,16)
    dim3 gkv(NKV * HD / 128, S_LEN / 128);  // (8,16)
    // Top-k-critical paths: PROVEN fp32 arithmetic (R6).
    sgemm_nt<<<gq,  256>>>(hidden, Wq, q, S_LEN, HID, HID);
    sgemm_nt<<<gkv, 256>>>(hidden, Wk, k, S_LEN, NKV * HD, HID);
    // Smooth (value) paths: 3xTF32 tensor cores.
    gemm3xtf32<<<gkv, 256>>>(hidden, Wv, v, S_LEN, NKV * HD, HID);

    rope_apply_kernel<<<(S_LEN * NH * 64 + 255) / 256, 256>>>(q, NH);
    rope_apply_kernel<<<(S_LEN * NKV * 64 + 255) / 256, 256>>>(k, NKV);

    size_t smem = (size_t)(2 * 64 * 132 + 64 * 64 + 64 * TOPK) * 4 + 64 * TOPK * 4;
    cudaFuncSetAttribute(attn_kernel, cudaFuncAttributeMaxDynamicSharedMemorySize,
                         (int)smem);
    attn_kernel<<<dim3(S_LEN / 64, NH), 256, smem>>>(q, k, v, at);

    gemm3xtf32<<<gq, 256>>>(at, Wo, out, S_LEN, HID, HID);
}

// round 9
// speedup vs baseline: 1.0107x; 1.0107x over previous
#include <cuda_runtime.h>
#include <math.h>
#include <stdint.h>

#define S_LEN 2048
#define HID   4096
#define NH    32
#define NKV   8
#define HD    128
#define TOPK  16

// ---------------- scratch (device globals: no allocations allowed) ----------
__device__ float g_Q[(size_t)S_LEN * HID];        // 32 MB
__device__ float g_K[(size_t)S_LEN * NKV * HD];   // 8 MB
__device__ float g_V[(size_t)S_LEN * NKV * HD];   // 8 MB
__device__ float g_attn[(size_t)S_LEN * HID];     // 32 MB
__device__ float g_cos[S_LEN * 64];
__device__ float g_sin[S_LEN * 64];

// ---------------- packed f32x2 helpers (sm_103a FFMA2) ----------------------
// fma.rn.f32x2: two independent lane-wise rn FMAs per issue slot.
// Per-lane arithmetic identical to scalar fmaf -> bitwise-preserving.
__device__ __forceinline__ void ffma2(uint64_t& c, uint64_t a, uint64_t b) {
    asm("fma.rn.f32x2 %0, %1, %2, %0;" : "+l"(c) : "l"(a), "l"(b));
}
__device__ __forceinline__ uint64_t pack2(float lo, float hi) {
    uint64_t r;
    asm("mov.b64 %0, {%1, %2};" : "=l"(r) : "f"(lo), "f"(hi));
    return r;
}
__device__ __forceinline__ void unpack2(uint64_t v, float& lo, float& hi) {
    asm("mov.b64 {%0, %1}, %2;" : "=f"(lo), "=f"(hi) : "l"(v));
}

// ---------------- RoPE table (host/correctly-rounded math emulation) --------
// DO NOT TOUCH: this exact pipeline is what makes the kernel pass.
__global__ void rope_table_kernel() {
    int idx = blockIdx.x * blockDim.x + threadIdx.x;
    if (idx >= S_LEN * 64) return;
    int s = idx >> 6;
    int i = idx & 63;
    double expo = (double)(2 * i) / 128.0;            // exact
    float  p    = (float)pow(500000.0, expo);         // CR powf emulation
    float  inv  = __fdiv_rn(1.0f, p);
    float  ang  = __fmul_rn((float)s, inv);
    g_cos[idx] = (float)cos((double)ang);             // CR cosf emulation
    g_sin[idx] = (float)sin((double)ang);             // CR sinf emulation
}

// ---------------- RoPE apply (in place, explicit rn mul/add, no FMA) --------
__global__ void rope_apply_kernel(float* __restrict__ X, int nheads) {
    int idx = blockIdx.x * blockDim.x + threadIdx.x;
    int total = S_LEN * nheads * 64;
    if (idx >= total) return;
    int i = idx & 63;
    int h = (idx >> 6) % nheads;
    int s = idx / (nheads * 64);
    size_t base = ((size_t)s * nheads + h) * HD + i;
    float c  = g_cos[(s << 6) + i];
    float sn = g_sin[(s << 6) + i];
    float x1 = X[base];
    float x2 = X[base + 64];
    float t1 = __fmul_rn(x1, c);
    float t2 = __fmul_rn(x2, sn);
    float u1 = __fmul_rn(x2, c);
    float u2 = __fmul_rn(x1, sn);
    X[base]      = __fadd_rn(t1, -t2);
    X[base + 64] = __fadd_rn(u1, u2);
}

// ---------------- fp32 SGEMM with FFMA2: C[M,N] = A[M,K] @ B[N,K]^T --------
// BM=BN=128, BK=16, 256 threads, 8x8 per thread (packed as 8x4 f32x2),
// register prefetch. Per-element accumulation order identical to scalar fp32.
__device__ __forceinline__ void sgemm_body(
    const float* __restrict__ A, const float* __restrict__ B,
    float* __restrict__ C, int M, int N, int K, int bm, int bn)
{
    __shared__ float As[16 * 132];  // [k][m], padded
    __shared__ float Bs[16 * 132];  // [k][n], padded

    const int tid = threadIdx.x;
    const int lr = tid >> 2;            // 0..63
    const int lc = (tid & 3) << 2;      // 0,4,8,12
    const int ty = tid >> 4;            // 0..15
    const int tx = tid & 15;            // 0..15

    uint64_t acc2[8][4];
#pragma unroll
    for (int i = 0; i < 8; i++)
#pragma unroll
        for (int jp = 0; jp < 4; jp++) acc2[i][jp] = 0ull;

    const float* Ap = A + (size_t)(bm + lr) * K + lc;
    const float* Bp = B + (size_t)(bn + lr) * K + lc;

    float4 a0 = *(const float4*)(Ap);
    float4 a1 = *(const float4*)(Ap + (size_t)64 * K);
    float4 b0 = *(const float4*)(Bp);
    float4 b1 = *(const float4*)(Bp + (size_t)64 * K);

    for (int k0 = 0; k0 < K; k0 += 16) {
        __syncthreads();
        As[(lc + 0) * 132 + lr] = a0.x;
        As[(lc + 1) * 132 + lr] = a0.y;
        As[(lc + 2) * 132 + lr] = a0.z;
        As[(lc + 3) * 132 + lr] = a0.w;
        As[(lc + 0) * 132 + lr + 64] = a1.x;
        As[(lc + 1) * 132 + lr + 64] = a1.y;
        As[(lc + 2) * 132 + lr + 64] = a1.z;
        As[(lc + 3) * 132 + lr + 64] = a1.w;
        Bs[(lc + 0) * 132 + lr] = b0.x;
        Bs[(lc + 1) * 132 + lr] = b0.y;
        Bs[(lc + 2) * 132 + lr] = b0.z;
        Bs[(lc + 3) * 132 + lr] = b0.w;
        Bs[(lc + 0) * 132 + lr + 64] = b1.x;
        Bs[(lc + 1) * 132 + lr + 64] = b1.y;
        Bs[(lc + 2) * 132 + lr + 64] = b1.z;
        Bs[(lc + 3) * 132 + lr + 64] = b1.w;
        __syncthreads();

        if (k0 + 16 < K) {
            a0 = *(const float4*)(Ap + k0 + 16);
            a1 = *(const float4*)(Ap + (size_t)64 * K + k0 + 16);
            b0 = *(const float4*)(Bp + k0 + 16);
            b1 = *(const float4*)(Bp + (size_t)64 * K + k0 + 16);
        }

#pragma unroll
        for (int kk = 0; kk < 16; kk++) {
            float ar[8], br[8];
            *(float4*)(ar)     = *(float4*)&As[kk * 132 + ty * 8];
            *(float4*)(ar + 4) = *(float4*)&As[kk * 132 + ty * 8 + 4];
            *(float4*)(br)     = *(float4*)&Bs[kk * 132 + tx * 8];
            *(float4*)(br + 4) = *(float4*)&Bs[kk * 132 + tx * 8 + 4];
            uint64_t b2[4];
            b2[0] = pack2(br[0], br[1]);
            b2[1] = pack2(br[2], br[3]);
            b2[2] = pack2(br[4], br[5]);
            b2[3] = pack2(br[6], br[7]);
#pragma unroll
            for (int i = 0; i < 8; i++) {
                uint64_t a2 = pack2(ar[i], ar[i]);
                ffma2(acc2[i][0], a2, b2[0]);
                ffma2(acc2[i][1], a2, b2[1]);
                ffma2(acc2[i][2], a2, b2[2]);
                ffma2(acc2[i][3], a2, b2[3]);
            }
        }
    }

#pragma unroll
    for (int i = 0; i < 8; i++) {
        size_t row = (size_t)(bm + ty * 8 + i) * N + bn + tx * 8;
        float c0, c1, c2, c3, c4, c5, c6, c7;
        unpack2(acc2[i][0], c0, c1);
        unpack2(acc2[i][1], c2, c3);
        unpack2(acc2[i][2], c4, c5);
        unpack2(acc2[i][3], c6, c7);
        *(float4*)&C[row]     = make_float4(c0, c1, c2, c3);
        *(float4*)&C[row + 4] = make_float4(c4, c5, c6, c7);
    }
}

__global__ __launch_bounds__(256) void sgemm_nt(
    const float* __restrict__ A, const float* __restrict__ B,
    float* __restrict__ C, int M, int N, int K)
{
    sgemm_body(A, B, C, M, N, K, blockIdx.y * 128, blockIdx.x * 128);
}

// K and V projections fused in one launch (blockIdx.z selects path)
__global__ __launch_bounds__(256) void sgemm_kv(
    const float* __restrict__ A,
    const float* __restrict__ Wk, const float* __restrict__ Wv,
    float* __restrict__ Ko, float* __restrict__ Vo)
{
    const float* B = blockIdx.z ? Wv : Wk;
    float*       C = blockIdx.z ? Vo : Ko;
    sgemm_body(A, B, C, S_LEN, NKV * HD, HID, blockIdx.y * 128, blockIdx.x * 128);
}

// ---------------- fused top-k attention (FFMA2 score dot) ------------------
// grid (S/64, NH), 256 threads.
__global__ __launch_bounds__(256) void attn_kernel(
    const float* __restrict__ Q, const float* __restrict__ Kd,
    const float* __restrict__ V, float* __restrict__ O)
{
    extern __shared__ float sm[];
    float* Qs = sm;                      // [64][132]
    float* Ks = Qs + 64 * 132;           // [64][132]
    float* Ss = Ks + 64 * 132;           // [64][64]
    float* Tv = Ss + 64 * 64;            // [64][16] values -> weights
    int*   Ti = (int*)(Tv + 64 * TOPK);  // [64][16]

    const int tid = threadIdx.x;
    const int h   = blockIdx.y;
    const int kvh = h >> 2;
    const int q0  = blockIdx.x * 64;
    const float sqrtd = 11.313708498984761f;  // f32(sqrt(128))

#pragma unroll
    for (int it = 0; it < 8; it++) {
        int idx = tid + it * 256;
        int r = idx >> 5;
        int d4 = (idx & 31) << 2;
        float4 v = *(const float4*)&Q[((size_t)(q0 + r) * NH + h) * HD + d4];
        *(float4*)&Qs[r * 132 + d4] = v;
    }
    if (tid < 64) {
#pragma unroll
        for (int j = 0; j < TOPK; j++) Tv[tid * TOPK + j] = -INFINITY;
    }
    float vmin = -INFINITY;
    int minpos = 0;

    const int ty = tid >> 4, tx = tid & 15;
    const int r0 = ty << 2, c0 = tx << 2;

    for (int kt = 0; kt < S_LEN / 64; kt++) {
        __syncthreads();
#pragma unroll
        for (int it = 0; it < 8; it++) {
            int idx = tid + it * 256;
            int r = idx >> 5;
            int d4 = (idx & 31) << 2;
            float4 v = *(const float4*)&Kd[((size_t)(kt * 64 + r) * NKV + kvh) * HD + d4];
            *(float4*)&Ks[r * 132 + d4] = v;
        }
        __syncthreads();

        // 4x4 micro-tile scores, packed as 4x2 f32x2; per-element order
        // (x,y,z,w within each d-quad, d ascending) identical to scalar.
        uint64_t acc2[4][2];
#pragma unroll
        for (int i = 0; i < 4; i++) { acc2[i][0] = 0ull; acc2[i][1] = 0ull; }

        const float* qp = Qs + r0 * 132;
        const float* kp = Ks + c0 * 132;
#pragma unroll
        for (int d = 0; d < 128; d += 4) {
            float4 A0 = *(const float4*)(qp + d);
            float4 A1 = *(const float4*)(qp + 132 + d);
            float4 A2 = *(const float4*)(qp + 264 + d);
            float4 A3 = *(const float4*)(qp + 396 + d);
            float4 B0 = *(const float4*)(kp + d);
            float4 B1 = *(const float4*)(kp + 132 + d);
            float4 B2 = *(const float4*)(kp + 264 + d);
            float4 B3 = *(const float4*)(kp + 396 + d);
            const float4 Ax[4] = {A0, A1, A2, A3};
#pragma unroll
            for (int cmp = 0; cmp < 4; cmp++) {
                float b0c = cmp == 0 ? B0.x : cmp == 1 ? B0.y : cmp == 2 ? B0.z : B0.w;
                float b1c = cmp == 0 ? B1.x : cmp == 1 ? B1.y : cmp == 2 ? B1.z : B1.w;
                float b2c = cmp == 0 ? B2.x : cmp == 1 ? B2.y : cmp == 2 ? B2.z : B2.w;
                float b3c = cmp == 0 ? B3.x : cmp == 1 ? B3.y : cmp == 2 ? B3.z : B3.w;
                uint64_t b01 = pack2(b0c, b1c);
                uint64_t b23 = pack2(b2c, b3c);
#pragma unroll
                for (int i = 0; i < 4; i++) {
                    float ac = cmp == 0 ? Ax[i].x : cmp == 1 ? Ax[i].y
                             : cmp == 2 ? Ax[i].z : Ax[i].w;
                    uint64_t a2 = pack2(ac, ac);
                    ffma2(acc2[i][0], a2, b01);
                    ffma2(acc2[i][1], a2, b23);
                }
            }
        }
#pragma unroll
        for (int i = 0; i < 4; i++) {
            float s0, s1, s2, s3;
            unpack2(acc2[i][0], s0, s1);
            unpack2(acc2[i][1], s2, s3);
            Ss[(r0 + i) * 64 + c0 + 0] = __fdiv_rn(s0, sqrtd);
            Ss[(r0 + i) * 64 + c0 + 1] = __fdiv_rn(s1, sqrtd);
            Ss[(r0 + i) * 64 + c0 + 2] = __fdiv_rn(s2, sqrtd);
            Ss[(r0 + i) * 64 + c0 + 3] = __fdiv_rn(s3, sqrtd);
        }
        __syncthreads();

        // per-row top-16 maintenance (threads 0..63, one per q row)
        if (tid < 64) {
            int base = kt * 64;
            float* tvp = Tv + tid * TOPK;
            int*   tip = Ti + tid * TOPK;
            const float* srow = Ss + tid * 64;
            for (int c = 0; c < 64; c++) {
                float s = srow[c];
                if (s > vmin) {
                    tvp[minpos] = s;
                    tip[minpos] = base + c;
                    vmin = tvp[0]; minpos = 0;
#pragma unroll
                    for (int j = 1; j < TOPK; j++) {
                        float t = tvp[j];
                        if (t < vmin) { vmin = t; minpos = j; }
                    }
                }
            }
        }
    }
    __syncthreads();

    // softmax over top-16 per row
    if (tid < 64) {
        float* tvp = Tv + tid * TOPK;
        float m = -INFINITY;
#pragma unroll
        for (int j = 0; j < TOPK; j++) m = fmaxf(m, tvp[j]);
        float ssum = 0.0f;
#pragma unroll
        for (int j = 0; j < TOPK; j++) {
            float e = expf(tvp[j] - m);
            tvp[j] = e;
            ssum += e;
        }
        float inv = __fdiv_rn(1.0f, ssum);
#pragma unroll
        for (int j = 0; j < TOPK; j++) tvp[j] = __fmul_rn(tvp[j], inv);
    }
    __syncthreads();

    // weighted V gather: 64 rows x 128 dims
#pragma unroll
    for (int it = 0; it < 32; it++) {
        int idx = tid + it * 256;
        int r = idx >> 7;
        int d = idx & 127;
        const float* tvp = Tv + r * TOPK;
        const int*   tip = Ti + r * TOPK;
        float acc = 0.0f;
#pragma unroll
        for (int j = 0; j < TOPK; j++) {
            float w = tvp[j];
            int ki = tip[j];
            acc = fmaf(w, V[((size_t)ki * NKV + kvh) * HD + d], acc);
        }
        O[((size_t)(q0 + r) * NH + h) * HD + d] = acc;
    }
}

// ---------------- launch ----------------------------------------------------
extern "C" void kernel_launch(void* const* d_in, const int* in_sizes, int n_in,
                              void* d_out, int out_size)
{
    const float* hidden = (const float*)d_in[0];
    const float* Wq = (const float*)d_in[1];
    const float* Wk = (const float*)d_in[2];
    const float* Wv = (const float*)d_in[3];
    const float* Wo = (const float*)d_in[4];
    float* out = (float*)d_out;

    float *q, *k, *v, *at;
    cudaGetSymbolAddress((void**)&q,  g_Q);
    cudaGetSymbolAddress((void**)&k,  g_K);
    cudaGetSymbolAddress((void**)&v,  g_V);
    cudaGetSymbolAddress((void**)&at, g_attn);

    rope_table_kernel<<<(S_LEN * 64 + 255) / 256, 256>>>();

    dim3 gq(HID / 128, S_LEN / 128);            // (32,16)
    dim3 gkv(NKV * HD / 128, S_LEN / 128, 2);   // (8,16,2) — K and V fused
    sgemm_nt<<<gq, 256>>>(hidden, Wq, q, S_LEN, HID, HID);
    sgemm_kv<<<gkv, 256>>>(hidden, Wk, Wv, k, v);

    rope_apply_kernel<<<(S_LEN * NH * 64 + 255) / 256, 256>>>(q, NH);
    rope_apply_kernel<<<(S_LEN * NKV * 64 + 255) / 256, 256>>>(k, NKV);

    size_t smem = (size_t)(2 * 64 * 132 + 64 * 64 + 64 * TOPK) * 4 + 64 * TOPK * 4;
    cudaFuncSetAttribute(attn_kernel, cudaFuncAttributeMaxDynamicSharedMemorySize,
                         (int)smem);
    attn_kernel<<<dim3(S_LEN / 64, NH), 256, smem>>>(q, k, v, at);

    sgemm_nt<<<gq, 256>>>(at, Wo, out, S_LEN, HID, HID);
}

// round 10
// speedup vs baseline: 1.1951x; 1.1825x over previous
#include <cuda_runtime.h>
#include <math.h>
#include <stdint.h>

#define S_LEN 2048
#define HID   4096
#define NH    32
#define NKV   8
#define HD    128
#define TOPK  16

// ---------------- scratch (device globals: no allocations allowed) ----------
__device__ float g_Q[(size_t)S_LEN * HID];        // 32 MB
__device__ float g_K[(size_t)S_LEN * NKV * HD];   // 8 MB
__device__ float g_V[(size_t)S_LEN * NKV * HD];   // 8 MB
__device__ float g_attn[(size_t)S_LEN * HID];     // 32 MB
__device__ float g_cos[S_LEN * 64];
__device__ float g_sin[S_LEN * 64];

// ---------------- RoPE table (host/correctly-rounded math emulation) --------
// DO NOT TOUCH: this exact pipeline is what makes the kernel pass.
__global__ void rope_table_kernel() {
    int idx = blockIdx.x * blockDim.x + threadIdx.x;
    if (idx >= S_LEN * 64) return;
    int s = idx >> 6;
    int i = idx & 63;
    double expo = (double)(2 * i) / 128.0;            // exact
    float  p    = (float)pow(500000.0, expo);         // CR powf emulation
    float  inv  = __fdiv_rn(1.0f, p);
    float  ang  = __fmul_rn((float)s, inv);
    g_cos[idx] = (float)cos((double)ang);             // CR cosf emulation
    g_sin[idx] = (float)sin((double)ang);             // CR sinf emulation
}

// ---------------- RoPE apply (in place, explicit rn mul/add, no FMA) --------
__global__ void rope_apply_kernel(float* __restrict__ X, int nheads) {
    int idx = blockIdx.x * blockDim.x + threadIdx.x;
    int total = S_LEN * nheads * 64;
    if (idx >= total) return;
    int i = idx & 63;
    int h = (idx >> 6) % nheads;
    int s = idx / (nheads * 64);
    size_t base = ((size_t)s * nheads + h) * HD + i;
    float c  = g_cos[(s << 6) + i];
    float sn = g_sin[(s << 6) + i];
    float x1 = X[base];
    float x2 = X[base + 64];
    float t1 = __fmul_rn(x1, c);
    float t2 = __fmul_rn(x2, sn);
    float u1 = __fmul_rn(x2, c);
    float u2 = __fmul_rn(x1, sn);
    X[base]      = __fadd_rn(t1, -t2);
    X[base + 64] = __fadd_rn(u1, u2);
}

// ---------------- fp32 SGEMM: C[M,N] = A[M,K] @ B[N,K]^T -------------------
// BM=BN=128, BK=16, 256 threads, 8x8 per thread, register prefetch +
// DOUBLE-BUFFERED smem (one sync per k-tile). Arithmetic order unchanged.
__device__ __forceinline__ void sgemm_body(
    const float* __restrict__ A, const float* __restrict__ B,
    float* __restrict__ C, int M, int N, int K, int bm, int bn)
{
    __shared__ float As[2][16 * 132];  // [k][m], padded
    __shared__ float Bs[2][16 * 132];  // [k][n], padded

    const int tid = threadIdx.x;
    const int lr = tid >> 2;            // 0..63
    const int lc = (tid & 3) << 2;      // 0,4,8,12
    const int ty = tid >> 4;            // 0..15
    const int tx = tid & 15;            // 0..15

    float acc[8][8];
#pragma unroll
    for (int i = 0; i < 8; i++)
#pragma unroll
        for (int j = 0; j < 8; j++) acc[i][j] = 0.0f;

    const float* Ap = A + (size_t)(bm + lr) * K + lc;
    const float* Bp = B + (size_t)(bn + lr) * K + lc;

    // tile 0 -> buffer 0
    {
        float4 a0 = *(const float4*)(Ap);
        float4 a1 = *(const float4*)(Ap + (size_t)64 * K);
        float4 b0 = *(const float4*)(Bp);
        float4 b1 = *(const float4*)(Bp + (size_t)64 * K);
        As[0][(lc + 0) * 132 + lr] = a0.x;
        As[0][(lc + 1) * 132 + lr] = a0.y;
        As[0][(lc + 2) * 132 + lr] = a0.z;
        As[0][(lc + 3) * 132 + lr] = a0.w;
        As[0][(lc + 0) * 132 + lr + 64] = a1.x;
        As[0][(lc + 1) * 132 + lr + 64] = a1.y;
        As[0][(lc + 2) * 132 + lr + 64] = a1.z;
        As[0][(lc + 3) * 132 + lr + 64] = a1.w;
        Bs[0][(lc + 0) * 132 + lr] = b0.x;
        Bs[0][(lc + 1) * 132 + lr] = b0.y;
        Bs[0][(lc + 2) * 132 + lr] = b0.z;
        Bs[0][(lc + 3) * 132 + lr] = b0.w;
        Bs[0][(lc + 0) * 132 + lr + 64] = b1.x;
        Bs[0][(lc + 1) * 132 + lr + 64] = b1.y;
        Bs[0][(lc + 2) * 132 + lr + 64] = b1.z;
        Bs[0][(lc + 3) * 132 + lr + 64] = b1.w;
    }
    __syncthreads();

    int cur = 0;
    for (int k0 = 0; k0 < K; k0 += 16) {
        float4 a0, a1, b0, b1;
        const bool more = (k0 + 16 < K);
        if (more) {
            a0 = *(const float4*)(Ap + k0 + 16);
            a1 = *(const float4*)(Ap + (size_t)64 * K + k0 + 16);
            b0 = *(const float4*)(Bp + k0 + 16);
            b1 = *(const float4*)(Bp + (size_t)64 * K + k0 + 16);
        }

        const float* Asc = As[cur];
        const float* Bsc = Bs[cur];
#pragma unroll
        for (int kk = 0; kk < 16; kk++) {
            float ar[8], br[8];
            *(float4*)(ar)     = *(const float4*)&Asc[kk * 132 + ty * 8];
            *(float4*)(ar + 4) = *(const float4*)&Asc[kk * 132 + ty * 8 + 4];
            *(float4*)(br)     = *(const float4*)&Bsc[kk * 132 + tx * 8];
            *(float4*)(br + 4) = *(const float4*)&Bsc[kk * 132 + tx * 8 + 4];
#pragma unroll
            for (int i = 0; i < 8; i++)
#pragma unroll
                for (int j = 0; j < 8; j++)
                    acc[i][j] = fmaf(ar[i], br[j], acc[i][j]);
        }

        if (more) {
            int nxt = cur ^ 1;
            As[nxt][(lc + 0) * 132 + lr] = a0.x;
            As[nxt][(lc + 1) * 132 + lr] = a0.y;
            As[nxt][(lc + 2) * 132 + lr] = a0.z;
            As[nxt][(lc + 3) * 132 + lr] = a0.w;
            As[nxt][(lc + 0) * 132 + lr + 64] = a1.x;
            As[nxt][(lc + 1) * 132 + lr + 64] = a1.y;
            As[nxt][(lc + 2) * 132 + lr + 64] = a1.z;
            As[nxt][(lc + 3) * 132 + lr + 64] = a1.w;
            Bs[nxt][(lc + 0) * 132 + lr] = b0.x;
            Bs[nxt][(lc + 1) * 132 + lr] = b0.y;
            Bs[nxt][(lc + 2) * 132 + lr] = b0.z;
            Bs[nxt][(lc + 3) * 132 + lr] = b0.w;
            Bs[nxt][(lc + 0) * 132 + lr + 64] = b1.x;
            Bs[nxt][(lc + 1) * 132 + lr + 64] = b1.y;
            Bs[nxt][(lc + 2) * 132 + lr + 64] = b1.z;
            Bs[nxt][(lc + 3) * 132 + lr + 64] = b1.w;
            __syncthreads();
            cur = nxt;
        }
    }

#pragma unroll
    for (int i = 0; i < 8; i++) {
        size_t row = (size_t)(bm + ty * 8 + i) * N + bn + tx * 8;
        float4 v0 = make_float4(acc[i][0], acc[i][1], acc[i][2], acc[i][3]);
        float4 v1 = make_float4(acc[i][4], acc[i][5], acc[i][6], acc[i][7]);
        *(float4*)&C[row]     = v0;
        *(float4*)&C[row + 4] = v1;
    }
}

__global__ __launch_bounds__(256) void sgemm_nt(
    const float* __restrict__ A, const float* __restrict__ B,
    float* __restrict__ C, int M, int N, int K)
{
    sgemm_body(A, B, C, M, N, K, blockIdx.y * 128, blockIdx.x * 128);
}

// K and V projections fused in one launch (blockIdx.z selects path)
__global__ __launch_bounds__(256) void sgemm_kv(
    const float* __restrict__ A,
    const float* __restrict__ Wk, const float* __restrict__ Wv,
    float* __restrict__ Ko, float* __restrict__ Vo)
{
    const float* B = blockIdx.z ? Wv : Wk;
    float*       C = blockIdx.z ? Vo : Ko;
    sgemm_body(A, B, C, S_LEN, NKV * HD, HID, blockIdx.y * 128, blockIdx.x * 128);
}

// ---------------- fused top-k attention ------------------------------------
// grid (S/128, NH), 256 threads. Block: 128 q-rows x full K sweep in
// 128-col tiles. Q/K in TRANSPOSED smem [d][row] (conflict-free fragment
// reads), 16x16 threads x 8x8 micro-tile (GEMM-grade FMA:LDS ratio).
// Score FMA chain: single ascending-d sequence -> bitwise same as before.
#define APAD 132

__global__ __launch_bounds__(256) void attn_kernel(
    const float* __restrict__ Q, const float* __restrict__ Kd,
    const float* __restrict__ V, float* __restrict__ O)
{
    extern __shared__ float sm[];
    float* Qs = sm;                        // [128][APAD]  Qs[d*APAD + qr]
    float* Ks = Qs + 128 * APAD;           // [128][APAD]  Ks[d*APAD + kc]
    float* Ss = Ks + 128 * APAD;           // [128][128]
    float* Tv = Ss + 128 * 128;            // [128][16]
    int*   Ti = (int*)(Tv + 128 * TOPK);   // [128][16]

    const int tid = threadIdx.x;
    const int h   = blockIdx.y;
    const int kvh = h >> 2;
    const int q0  = blockIdx.x * 128;
    const float sqrtd = 11.313708498984761f;  // f32(sqrt(128))

    // load Q tile transposed: lane r = idx&127 (rows), dq = idx>>7 (0..31)
#pragma unroll
    for (int it = 0; it < 16; it++) {
        int idx = tid + it * 256;
        int r  = idx & 127;
        int dq = idx >> 7;
        float4 v = *(const float4*)&Q[((size_t)(q0 + r) * NH + h) * HD + dq * 4];
        Qs[(dq * 4 + 0) * APAD + r] = v.x;
        Qs[(dq * 4 + 1) * APAD + r] = v.y;
        Qs[(dq * 4 + 2) * APAD + r] = v.z;
        Qs[(dq * 4 + 3) * APAD + r] = v.w;
    }
    if (tid < 128) {
#pragma unroll
        for (int j = 0; j < TOPK; j++) Tv[tid * TOPK + j] = -INFINITY;
    }
    float vmin = -INFINITY;
    int minpos = 0;

    const int ty = tid >> 4, tx = tid & 15;

    for (int kt = 0; kt < S_LEN / 128; kt++) {
        __syncthreads();   // prev top-k done with Ss; prev compute done with Ks
        // load K tile transposed
#pragma unroll
        for (int it = 0; it < 16; it++) {
            int idx = tid + it * 256;
            int c  = idx & 127;
            int dq = idx >> 7;
            float4 v = *(const float4*)&Kd[((size_t)(kt * 128 + c) * NKV + kvh) * HD + dq * 4];
            Ks[(dq * 4 + 0) * APAD + c] = v.x;
            Ks[(dq * 4 + 1) * APAD + c] = v.y;
            Ks[(dq * 4 + 2) * APAD + c] = v.z;
            Ks[(dq * 4 + 3) * APAD + c] = v.w;
        }
        __syncthreads();

        // 8x8 micro-tile scores over d = 0..127 (ascending chain, bitwise)
        float acc[8][8];
#pragma unroll
        for (int i = 0; i < 8; i++)
#pragma unroll
            for (int j = 0; j < 8; j++) acc[i][j] = 0.0f;

#pragma unroll 8
        for (int d = 0; d < 128; d++) {
            float ar[8], br[8];
            *(float4*)(ar)     = *(const float4*)&Qs[d * APAD + ty * 8];
            *(float4*)(ar + 4) = *(const float4*)&Qs[d * APAD + ty * 8 + 4];
            *(float4*)(br)     = *(const float4*)&Ks[d * APAD + tx * 8];
            *(float4*)(br + 4) = *(const float4*)&Ks[d * APAD + tx * 8 + 4];
#pragma unroll
            for (int i = 0; i < 8; i++)
#pragma unroll
                for (int j = 0; j < 8; j++)
                    acc[i][j] = fmaf(ar[i], br[j], acc[i][j]);
        }

#pragma unroll
        for (int i = 0; i < 8; i++) {
            float4 s0 = make_float4(__fdiv_rn(acc[i][0], sqrtd),
                                    __fdiv_rn(acc[i][1], sqrtd),
                                    __fdiv_rn(acc[i][2], sqrtd),
                                    __fdiv_rn(acc[i][3], sqrtd));
            float4 s1 = make_float4(__fdiv_rn(acc[i][4], sqrtd),
                                    __fdiv_rn(acc[i][5], sqrtd),
                                    __fdiv_rn(acc[i][6], sqrtd),
                                    __fdiv_rn(acc[i][7], sqrtd));
            *(float4*)&Ss[(ty * 8 + i) * 128 + tx * 8]     = s0;
            *(float4*)&Ss[(ty * 8 + i) * 128 + tx * 8 + 4] = s1;
        }
        __syncthreads();

        // per-row top-16 maintenance (threads 0..127, one per q row),
        // ascending column order -> same selection as before
        if (tid < 128) {
            int base = kt * 128;
            float* tvp = Tv + tid * TOPK;
            int*   tip = Ti + tid * TOPK;
            const float* srow = Ss + tid * 128;
            for (int c = 0; c < 128; c++) {
                float s = srow[c];
                if (s > vmin) {
                    tvp[minpos] = s;
                    tip[minpos] = base + c;
                    vmin = tvp[0]; minpos = 0;
#pragma unroll
                    for (int j = 1; j < TOPK; j++) {
                        float t = tvp[j];
                        if (t < vmin) { vmin = t; minpos = j; }
                    }
                }
            }
        }
    }
    __syncthreads();

    // softmax over top-16 per row
    if (tid < 128) {
        float* tvp = Tv + tid * TOPK;
        float m = -INFINITY;
#pragma unroll
        for (int j = 0; j < TOPK; j++) m = fmaxf(m, tvp[j]);
        float ssum = 0.0f;
#pragma unroll
        for (int j = 0; j < TOPK; j++) {
            float e = expf(tvp[j] - m);
            tvp[j] = e;
            ssum += e;
        }
        float inv = __fdiv_rn(1.0f, ssum);
#pragma unroll
        for (int j = 0; j < TOPK; j++) tvp[j] = __fmul_rn(tvp[j], inv);
    }
    __syncthreads();

    // weighted V gather: 128 rows x 128 dims
#pragma unroll
    for (int it = 0; it < 64; it++) {
        int idx = tid + it * 256;
        int r = idx >> 7;
        int d = idx & 127;
        const float* tvp = Tv + r * TOPK;
        const int*   tip = Ti + r * TOPK;
        float acc = 0.0f;
#pragma unroll
        for (int j = 0; j < TOPK; j++) {
            float w = tvp[j];
            int ki = tip[j];
            acc = fmaf(w, V[((size_t)ki * NKV + kvh) * HD + d], acc);
        }
        O[((size_t)(q0 + r) * NH + h) * HD + d] = acc;
    }
}

// ---------------- launch ----------------------------------------------------
extern "C" void kernel_launch(void* const* d_in, const int* in_sizes, int n_in,
                              void* d_out, int out_size)
{
    const float* hidden = (const float*)d_in[0];
    const float* Wq = (const float*)d_in[1];
    const float* Wk = (const float*)d_in[2];
    const float* Wv = (const float*)d_in[3];
    const float* Wo = (const float*)d_in[4];
    float* out = (float*)d_out;

    float *q, *k, *v, *at;
    cudaGetSymbolAddress((void**)&q,  g_Q);
    cudaGetSymbolAddress((void**)&k,  g_K);
    cudaGetSymbolAddress((void**)&v,  g_V);
    cudaGetSymbolAddress((void**)&at, g_attn);

    rope_table_kernel<<<(S_LEN * 64 + 255) / 256, 256>>>();

    dim3 gq(HID / 128, S_LEN / 128);            // (32,16)
    dim3 gkv(NKV * HD / 128, S_LEN / 128, 2);   // (8,16,2) — K and V fused
    sgemm_nt<<<gq, 256>>>(hidden, Wq, q, S_LEN, HID, HID);
    sgemm_kv<<<gkv, 256>>>(hidden, Wk, Wv, k, v);

    rope_apply_kernel<<<(S_LEN * NH * 64 + 255) / 256, 256>>>(q, NH);
    rope_apply_kernel<<<(S_LEN * NKV * 64 + 255) / 256, 256>>>(k, NKV);

    size_t smem = (size_t)(2 * 128 * APAD + 128 * 128 + 128 * TOPK) * 4
                + (size_t)128 * TOPK * 4;
    cudaFuncSetAttribute(attn_kernel, cudaFuncAttributeMaxDynamicSharedMemorySize,
                         (int)smem);
    attn_kernel<<<dim3(S_LEN / 128, NH), 256, smem>>>(q, k, v, at);

    sgemm_nt<<<gq, 256>>>(at, Wo, out, S_LEN, HID, HID);
}